// round 15
// baseline (speedup 1.0000x reference)
#include <cuda_runtime.h>
#include <cuda_bf16.h>
#include <cuda_fp16.h>
#include <cstdint>

#define NROWS 8192
#define BHALF 4096
#define KDIM  128
#define NBLK  64
#define PCTAS  296           // persistent CTAs (2 per SM)

typedef unsigned long long ull;

// Scratch (device globals — no allocation allowed in kernel_launch)
__device__ uint8_t g_X8[NROWS * KDIM];         // e4m3 copy of features
__device__ float g_sq[NROWS];                  // |x|^2 from fp8-rounded values
__device__ float g_row[NROWS];                 // full row sums of 8192x8192 kernel matrix
__device__ float g_logdiag[BHALF];             // log k12(i,i), fp32 path
__device__ float g_part[2];                    // partial sums for finalize
__device__ unsigned int g_cnt;                 // finalize block counter

static __device__ __forceinline__ uint32_t smem_u32(const void* p) {
    return (uint32_t)__cvta_generic_to_shared(p);
}

static __device__ __forceinline__ float rcp_approx(float x) {
    float r;
    asm("rcp.approx.ftz.f32 %0, %1;" : "=f"(r) : "f"(x));
    return r;
}

static __device__ __forceinline__ void cp_async16(uint32_t dst, const void* src) {
    asm volatile("cp.async.cg.shared.global [%0], [%1], 16;"
                 :: "r"(dst), "l"(src));
}
static __device__ __forceinline__ void cp_commit() {
    asm volatile("cp.async.commit_group;" ::: "memory");
}

// packed fp32 pair helpers (Blackwell FFMA2 path)
#define PACK2(o, lo, hi)  asm("mov.b64 %0, {%1, %2};" : "=l"(o) : "f"(lo), "f"(hi))
#define UNPACK2(lo, hi, i) asm("mov.b64 {%0, %1}, %2;" : "=f"(lo), "=f"(hi) : "l"(i))
#define ADDX2(o, a, b)     asm("add.rn.f32x2 %0, %1, %2;" : "=l"(o) : "l"(a), "l"(b))
#define FMAX2(o, a, b, c)  asm("fma.rn.f32x2 %0, %1, %2, %3;" : "=l"(o) : "l"(a), "l"(b), "l"(c))

// fp8 pack: lo = x, hi = y (cvt packs 2nd src operand into low half)
static __device__ __forceinline__ uint16_t f2_to_e4m3x2(float x, float y) {
    uint16_t r;
    asm("cvt.rn.satfinite.e4m3x2.f32 %0, %1, %2;" : "=h"(r) : "f"(y), "f"(x));
    return r;
}
static __device__ __forceinline__ float2 e4m3x2_to_f2(uint16_t q) {
    uint32_t h2;
    asm("cvt.rn.f16x2.e4m3x2 %0, %1;" : "=r"(h2) : "h"(q));
    return __half22float2(*(__half2*)&h2);
}

// ---------------------------------------------------------------------------
// K1: fused prep + diag. One warp per pair (i, i+4096).
// ---------------------------------------------------------------------------
__global__ void prep_kernel(const float* __restrict__ feat) {
    int w = threadIdx.x >> 5;
    int lane = threadIdx.x & 31;
    int p = blockIdx.x * 8 + w;           // 0..4095
    if (blockIdx.x == 0 && threadIdx.x == 0) {
        g_part[0] = 0.f; g_part[1] = 0.f; g_cnt = 0u;
    }
    if (p >= BHALF) return;
    float4 v1 = ((const float4*)(feat + (size_t)p * KDIM))[lane];
    float4 v2 = ((const float4*)(feat + (size_t)(p + BHALF) * KDIM))[lane];

    uint16_t q1a = f2_to_e4m3x2(v1.x, v1.y), q1b = f2_to_e4m3x2(v1.z, v1.w);
    uint16_t q2a = f2_to_e4m3x2(v2.x, v2.y), q2b = f2_to_e4m3x2(v2.z, v2.w);
    ((uint32_t*)(g_X8 + (size_t)p * KDIM))[lane] = (uint32_t)q1a | ((uint32_t)q1b << 16);
    ((uint32_t*)(g_X8 + (size_t)(p + BHALF) * KDIM))[lane] = (uint32_t)q2a | ((uint32_t)q2b << 16);

    float2 r1a = e4m3x2_to_f2(q1a), r1b = e4m3x2_to_f2(q1b);
    float2 r2a = e4m3x2_to_f2(q2a), r2b = e4m3x2_to_f2(q2b);
    float sb1 = r1a.x * r1a.x + r1a.y * r1a.y + r1b.x * r1b.x + r1b.y * r1b.y;
    float sb2 = r2a.x * r2a.x + r2a.y * r2a.y + r2b.x * r2b.x + r2b.y * r2b.y;
    float t1 = v1.x * v1.x + v1.y * v1.y + v1.z * v1.z + v1.w * v1.w;
    float t2 = v2.x * v2.x + v2.y * v2.y + v2.z * v2.z + v2.w * v2.w;
    float sd = v1.x * v2.x + v1.y * v2.y + v1.z * v2.z + v1.w * v2.w;

#pragma unroll
    for (int off = 16; off > 0; off >>= 1) {
        sb1 += __shfl_xor_sync(0xffffffff, sb1, off);
        sb2 += __shfl_xor_sync(0xffffffff, sb2, off);
        t1  += __shfl_xor_sync(0xffffffff, t1, off);
        t2  += __shfl_xor_sync(0xffffffff, t2, off);
        sd  += __shfl_xor_sync(0xffffffff, sd, off);
    }
    if (lane == 0) {
        g_sq[p] = sb1;
        g_sq[p + BHALF] = sb2;
        g_row[p] = 0.f;
        g_row[p + BHALF] = 0.f;
        float d2v = fmaxf(t1 + t2 - 2.f * sd, 0.f);
        g_logdiag[p] = -log1pf(d2v);
    }
}

// ---------------------------------------------------------------------------
// K2: persistent fp8 pairwise kernel — R8 structure, MUFU-halved epilogue.
// 296 CTAs x 7-8 upper-triangle 128x128 tiles, bi-major; A resident per
// chunk; B double-buffered via cp.async. mma.sync m16n8k32 e4m3, packed
// f32x2 Cauchy epilogue with paired reciprocal-of-product (2 RCP per 4
// elements instead of 4), shfl column sums.
// ---------------------------------------------------------------------------
#define LDS_STRIDE_B 144   // bytes per smem row: 128 data + 16 pad
#define TILE_BYTES (128 * LDS_STRIDE_B)        // 18432
#define PAIR_SMEM_BYTES (3 * TILE_BYTES)       // A + 2x B = 55296

__global__ void __launch_bounds__(256, 2) pair_kernel() {
    extern __shared__ __align__(16) char dynsm[];
    const uint32_t abase = smem_u32(dynsm);
    const uint32_t bbase0 = abase + TILE_BYTES;
    __shared__ float s_a[128];        // |x|^2 for A rows (raw)
    __shared__ float s_bb[2][128];    // |y|^2 for B rows (raw), per buffer

    const int tid = threadIdx.x;
    const int lane = tid & 31;
    const int wid = tid >> 5;

    // ---- chunk of tiles for this CTA ----
    const int b = blockIdx.x;
    const int start = b * 7 + (b < 8 ? b : 8);
    const int cnt = 7 + (b < 8 ? 1 : 0);
    int bi = 0, rem = start;
    while (rem >= NBLK - bi) { rem -= NBLK - bi; bi++; }
    int bj = bi + rem;

    auto issue_B = [&](int blk, int buf) {
        const char* g = (const char*)(g_X8 + (size_t)blk * 128 * KDIM);
        uint32_t sb = bbase0 + buf * TILE_BYTES;
#pragma unroll
        for (int it = 0; it < 4; it++) {
            int idx = tid + it * 256;          // 0..1023 (16B chunks)
            int r = idx >> 3, c = idx & 7;
            cp_async16(sb + r * LDS_STRIDE_B + c * 16, g + r * 128 + c * 16);
        }
        if (tid < 32)
            cp_async16(smem_u32(&s_bb[buf][0]) + tid * 16,
                       (const char*)(g_sq + blk * 128) + tid * 16);
    };
    auto issue_A = [&](int blk) {
        const char* g = (const char*)(g_X8 + (size_t)blk * 128 * KDIM);
#pragma unroll
        for (int it = 0; it < 4; it++) {
            int idx = tid + it * 256;
            int r = idx >> 3, c = idx & 7;
            cp_async16(abase + r * LDS_STRIDE_B + c * 16, g + r * 128 + c * 16);
        }
        if (tid < 32)
            cp_async16(smem_u32(&s_a[0]) + tid * 16,
                       (const char*)(g_sq + blk * 128) + tid * 16);
    };

    // ---- warp tiling: 4 (m) x 2 (n); warp tile = 32 x 64 ----
    const int rowbase = (wid & 3) * 32;
    const int colbase = (wid >> 2) * 64;
    const int lr = lane & 15;
    const int lc = lane >> 4;
    uint32_t aoff[2];
    uint32_t brel[4];
#pragma unroll
    for (int mi = 0; mi < 2; mi++)
        aoff[mi] = abase + (uint32_t)((rowbase + mi * 16 + lr) * LDS_STRIDE_B + lc * 16);
#pragma unroll
    for (int nq = 0; nq < 4; nq++)
        brel[nq] = (uint32_t)((colbase + nq * 16 + lr) * LDS_STRIDE_B + lc * 16);

    const int qr = lane >> 2;
    const int qc = (lane & 3) * 2;

    // ---- prime: A(bi) + B(bj) into buf 0 ----
    issue_A(bi);
    issue_B(bj, 0);
    cp_commit();
    bool need_cur = false;

    for (int i = 0; i < cnt; i++) {
        const int cur = i & 1;
        int nbi = bi, nbj = bj + 1;
        if (nbj == NBLK) { nbi++; nbj = nbi; }
        const bool have_next = (i + 1 < cnt);
        const bool same_bi = have_next && (nbi == bi);

        if (i > 0) __syncthreads();   // nobody still reads any buffer
        if (need_cur) {               // bi crossing: load A(bi)+B(bj,cur)
            issue_A(bi);
            issue_B(bj, cur);
            cp_commit();
        }
        if (same_bi) {                // prefetch next B during compute
            issue_B(nbj, cur ^ 1);
            cp_commit();
            asm volatile("cp.async.wait_group 1;" ::: "memory");
        } else {
            asm volatile("cp.async.wait_group 0;" ::: "memory");
        }
        __syncthreads();
        need_cur = have_next && (nbi != bi);

        const uint32_t bb = bbase0 + cur * TILE_BYTES;
        const float* s_b = s_bb[cur];
        const bool offdiag = (bi != bj);

        // ---- mma over K=128 fp8 (4 steps of 32) ----
        float acc[2][8][4];
#pragma unroll
        for (int mi = 0; mi < 2; mi++)
#pragma unroll
            for (int ni = 0; ni < 8; ni++)
#pragma unroll
                for (int r = 0; r < 4; r++) acc[mi][ni][r] = 0.f;

#pragma unroll
        for (int ks = 0; ks < 4; ks++) {
            uint32_t a[2][4];
            uint32_t bfr[8][2];
#pragma unroll
            for (int mi = 0; mi < 2; mi++) {
                asm volatile("ldmatrix.sync.aligned.m8n8.x4.shared.b16 {%0,%1,%2,%3}, [%4];"
                             : "=r"(a[mi][0]), "=r"(a[mi][1]), "=r"(a[mi][2]), "=r"(a[mi][3])
                             : "r"(aoff[mi] + ks * 32));
            }
#pragma unroll
            for (int nq = 0; nq < 4; nq++) {
                uint32_t r0, r1, r2, r3;
                asm volatile("ldmatrix.sync.aligned.m8n8.x4.shared.b16 {%0,%1,%2,%3}, [%4];"
                             : "=r"(r0), "=r"(r1), "=r"(r2), "=r"(r3)
                             : "r"(bb + brel[nq] + ks * 32));
                bfr[nq * 2 + 0][0] = r0; bfr[nq * 2 + 1][0] = r1;
                bfr[nq * 2 + 0][1] = r2; bfr[nq * 2 + 1][1] = r3;
            }
#pragma unroll
            for (int mi = 0; mi < 2; mi++)
#pragma unroll
                for (int ni = 0; ni < 8; ni++) {
                    asm volatile(
                        "mma.sync.aligned.m16n8k32.row.col.f32.e4m3.e4m3.f32 "
                        "{%0,%1,%2,%3}, {%4,%5,%6,%7}, {%8,%9}, {%0,%1,%2,%3};"
                        : "+f"(acc[mi][ni][0]), "+f"(acc[mi][ni][1]),
                          "+f"(acc[mi][ni][2]), "+f"(acc[mi][ni][3])
                        : "r"(a[mi][0]), "r"(a[mi][1]), "r"(a[mi][2]), "r"(a[mi][3]),
                          "r"(bfr[ni][0]), "r"(bfr[ni][1]));
                }
        }

        // ---- epilogue (packed f32x2, paired rcp-of-product: 2 MUFU / 4 elems)
        ull M2, ZER;
        PACK2(M2, -2.f, -2.f);
        PACK2(ZER, 0.f, 0.f);
        ull apk[2][2];
#pragma unroll
        for (int mi = 0; mi < 2; mi++) {
            float a0 = 1.f + s_a[rowbase + mi * 16 + qr];
            float a1 = 1.f + s_a[rowbase + mi * 16 + qr + 8];
            PACK2(apk[mi][0], a0, a0);
            PACK2(apk[mi][1], a1, a1);
        }
        ull rsp[2][2] = {{ZER, ZER}, {ZER, ZER}};

#pragma unroll
        for (int ni = 0; ni < 8; ni++) {
            float2 bp = *(const float2*)&s_b[colbase + ni * 8 + qc];
            ull bpk; PACK2(bpk, bp.x, bp.y);
            ull csp = ZER;
#pragma unroll
            for (int mi = 0; mi < 2; mi++) {
                ull t0, t1;
                ADDX2(t0, apk[mi][0], bpk);
                ADDX2(t1, apk[mi][1], bpk);
                ull a01, a23;
                PACK2(a01, acc[mi][ni][0], acc[mi][ni][1]);
                PACK2(a23, acc[mi][ni][2], acc[mi][ni][3]);
                ull d0, d1;
                FMAX2(d0, a01, M2, t0);
                FMAX2(d1, a23, M2, t1);
                float f00, f01, f10, f11;
                UNPACK2(f00, f01, d0);
                UNPACK2(f10, f11, d1);
                // paired reciprocal-of-product: 1/x = rcp(x*y)*y, 1/y = rcp(x*y)*x
                float r0 = rcp_approx(f00 * f01);
                float r1 = rcp_approx(f10 * f11);
                ull k01, k23;
                PACK2(k01, r0 * f01, r0 * f00);
                PACK2(k23, r1 * f11, r1 * f10);
                ADDX2(rsp[mi][0], rsp[mi][0], k01);
                ADDX2(rsp[mi][1], rsp[mi][1], k23);
                ADDX2(csp, csp, k01);
                ADDX2(csp, csp, k23);
            }
            if (offdiag) {
                float cs0, cs1;
                UNPACK2(cs0, cs1, csp);
                cs0 += __shfl_xor_sync(0xffffffff, cs0, 4);
                cs1 += __shfl_xor_sync(0xffffffff, cs1, 4);
                cs0 += __shfl_xor_sync(0xffffffff, cs0, 8);
                cs1 += __shfl_xor_sync(0xffffffff, cs1, 8);
                cs0 += __shfl_xor_sync(0xffffffff, cs0, 16);
                cs1 += __shfl_xor_sync(0xffffffff, cs1, 16);
                if (lane < 4) {
                    int cg = bj * 128 + colbase + ni * 8 + qc;
                    atomicAdd(g_row + cg, cs0);
                    atomicAdd(g_row + cg + 1, cs1);
                }
            }
        }
#pragma unroll
        for (int mi = 0; mi < 2; mi++) {
            float rs0, rs1, x, y;
            UNPACK2(x, y, rsp[mi][0]); rs0 = x + y;
            UNPACK2(x, y, rsp[mi][1]); rs1 = x + y;
            rs0 += __shfl_xor_sync(0xffffffff, rs0, 1);
            rs1 += __shfl_xor_sync(0xffffffff, rs1, 1);
            rs0 += __shfl_xor_sync(0xffffffff, rs0, 2);
            rs1 += __shfl_xor_sync(0xffffffff, rs1, 2);
            if ((lane & 3) == 0) {
                int r0 = bi * 128 + rowbase + mi * 16 + qr;
                atomicAdd(g_row + r0, rs0);
                atomicAdd(g_row + r0 + 8, rs1);
            }
        }

        bi = nbi; bj = nbj;
    }
}

// ---------------------------------------------------------------------------
// K3: parallel finalize.
// ---------------------------------------------------------------------------
__global__ void finalize_kernel(float* out) {
    const int tid = threadIdx.x;
    const int b = blockIdx.x;
    int row = b * 512 + tid;                 // 16*512 = 8192
    float an = __logf(g_row[row] - 1.0f);
    float ap = (tid < 256) ? g_logdiag[b * 256 + tid] : 0.f;
#pragma unroll
    for (int off = 16; off > 0; off >>= 1) {
        an += __shfl_xor_sync(0xffffffff, an, off);
        ap += __shfl_xor_sync(0xffffffff, ap, off);
    }
    __shared__ float sn[16], sp[16];
    int wid = tid >> 5, lane = tid & 31;
    if (lane == 0) { sn[wid] = an; sp[wid] = ap; }
    __syncthreads();
    if (tid == 0) {
        float tn = 0.f, tp = 0.f;
#pragma unroll
        for (int i = 0; i < 16; i++) { tn += sn[i]; tp += sp[i]; }
        atomicAdd(&g_part[0], tn);
        atomicAdd(&g_part[1], tp);
        __threadfence();
        unsigned int done = atomicAdd(&g_cnt, 1u);
        if (done == 15u) {
            float neg = *((volatile float*)&g_part[0]) / (2.0f * (float)BHALF);
            float pos = *((volatile float*)&g_part[1]) / (float)BHALF;
            out[0] = neg - pos;   // -(pos - neg)
        }
    }
}

// ---------------------------------------------------------------------------
extern "C" void kernel_launch(void* const* d_in, const int* in_sizes, int n_in,
                              void* d_out, int out_size) {
    const float* feat = (const float*)d_in[0];
    float* out = (float*)d_out;

    cudaFuncSetAttribute(pair_kernel,
                         cudaFuncAttributeMaxDynamicSharedMemorySize,
                         PAIR_SMEM_BYTES);

    prep_kernel<<<BHALF / 8, 256>>>(feat);
    pair_kernel<<<PCTAS, 256, PAIR_SMEM_BYTES>>>();
    finalize_kernel<<<16, 512>>>(out);
}

// round 16
// speedup vs baseline: 1.4221x; 1.4221x over previous
#include <cuda_runtime.h>
#include <cuda_bf16.h>
#include <cuda_fp16.h>
#include <cstdint>

#define NROWS 8192
#define BHALF 4096
#define KDIM  128
#define NBLK  64
#define PCTAS  296           // persistent CTAs (2 per SM)

typedef unsigned long long ull;

// Scratch (device globals — no allocation allowed in kernel_launch)
__device__ uint8_t g_X8[NROWS * KDIM];         // e4m3 copy of features
__device__ float g_sq[NROWS];                  // |x|^2 from fp8-rounded values
__device__ float g_row[NROWS];                 // full row sums of 8192x8192 kernel matrix
__device__ float g_logdiag[BHALF];             // log k12(i,i), fp32 path
__device__ float g_part[2];                    // partial sums for finalize
__device__ unsigned int g_cnt;                 // finalize block counter

static __device__ __forceinline__ uint32_t smem_u32(const void* p) {
    return (uint32_t)__cvta_generic_to_shared(p);
}

static __device__ __forceinline__ float rcp_approx(float x) {
    float r;
    asm("rcp.approx.ftz.f32 %0, %1;" : "=f"(r) : "f"(x));
    return r;
}

static __device__ __forceinline__ void cp_async16(uint32_t dst, const void* src) {
    asm volatile("cp.async.cg.shared.global [%0], [%1], 16;"
                 :: "r"(dst), "l"(src));
}
static __device__ __forceinline__ void cp_commit() {
    asm volatile("cp.async.commit_group;" ::: "memory");
}

// packed fp32 pair helpers (Blackwell FFMA2 path)
#define PACK2(o, lo, hi)  asm("mov.b64 %0, {%1, %2};" : "=l"(o) : "f"(lo), "f"(hi))
#define UNPACK2(lo, hi, i) asm("mov.b64 {%0, %1}, %2;" : "=f"(lo), "=f"(hi) : "l"(i))
#define ADDX2(o, a, b)     asm("add.rn.f32x2 %0, %1, %2;" : "=l"(o) : "l"(a), "l"(b))
#define FMAX2(o, a, b, c)  asm("fma.rn.f32x2 %0, %1, %2, %3;" : "=l"(o) : "l"(a), "l"(b), "l"(c))

// fp8 pack: lo = x, hi = y (cvt packs 2nd src operand into low half)
static __device__ __forceinline__ uint16_t f2_to_e4m3x2(float x, float y) {
    uint16_t r;
    asm("cvt.rn.satfinite.e4m3x2.f32 %0, %1, %2;" : "=h"(r) : "f"(y), "f"(x));
    return r;
}
static __device__ __forceinline__ float2 e4m3x2_to_f2(uint16_t q) {
    uint32_t h2;
    asm("cvt.rn.f16x2.e4m3x2 %0, %1;" : "=r"(h2) : "h"(q));
    return __half22float2(*(__half2*)&h2);
}

// ---------------------------------------------------------------------------
// K1: fused prep + diag. One warp per pair (i, i+4096).
// Converts to e4m3, computes |x|^2 from dequantized fp8 (consistent with mma),
// fp32 diagonal for the pos term.
// ---------------------------------------------------------------------------
__global__ void prep_kernel(const float* __restrict__ feat) {
    int w = threadIdx.x >> 5;
    int lane = threadIdx.x & 31;
    int p = blockIdx.x * 8 + w;           // 0..4095
    if (blockIdx.x == 0 && threadIdx.x == 0) {
        g_part[0] = 0.f; g_part[1] = 0.f; g_cnt = 0u;
    }
    if (p >= BHALF) return;
    float4 v1 = ((const float4*)(feat + (size_t)p * KDIM))[lane];
    float4 v2 = ((const float4*)(feat + (size_t)(p + BHALF) * KDIM))[lane];

    uint16_t q1a = f2_to_e4m3x2(v1.x, v1.y), q1b = f2_to_e4m3x2(v1.z, v1.w);
    uint16_t q2a = f2_to_e4m3x2(v2.x, v2.y), q2b = f2_to_e4m3x2(v2.z, v2.w);
    ((uint32_t*)(g_X8 + (size_t)p * KDIM))[lane] = (uint32_t)q1a | ((uint32_t)q1b << 16);
    ((uint32_t*)(g_X8 + (size_t)(p + BHALF) * KDIM))[lane] = (uint32_t)q2a | ((uint32_t)q2b << 16);

    float2 r1a = e4m3x2_to_f2(q1a), r1b = e4m3x2_to_f2(q1b);
    float2 r2a = e4m3x2_to_f2(q2a), r2b = e4m3x2_to_f2(q2b);
    float sb1 = r1a.x * r1a.x + r1a.y * r1a.y + r1b.x * r1b.x + r1b.y * r1b.y;
    float sb2 = r2a.x * r2a.x + r2a.y * r2a.y + r2b.x * r2b.x + r2b.y * r2b.y;
    float t1 = v1.x * v1.x + v1.y * v1.y + v1.z * v1.z + v1.w * v1.w;
    float t2 = v2.x * v2.x + v2.y * v2.y + v2.z * v2.z + v2.w * v2.w;
    float sd = v1.x * v2.x + v1.y * v2.y + v1.z * v2.z + v1.w * v2.w;

#pragma unroll
    for (int off = 16; off > 0; off >>= 1) {
        sb1 += __shfl_xor_sync(0xffffffff, sb1, off);
        sb2 += __shfl_xor_sync(0xffffffff, sb2, off);
        t1  += __shfl_xor_sync(0xffffffff, t1, off);
        t2  += __shfl_xor_sync(0xffffffff, t2, off);
        sd  += __shfl_xor_sync(0xffffffff, sd, off);
    }
    if (lane == 0) {
        g_sq[p] = sb1;
        g_sq[p + BHALF] = sb2;
        g_row[p] = 0.f;
        g_row[p + BHALF] = 0.f;
        float d2v = fmaxf(t1 + t2 - 2.f * sd, 0.f);
        g_logdiag[p] = -log1pf(d2v);
    }
}

// ---------------------------------------------------------------------------
// K2: persistent, software-pipelined fp8 pairwise kernel (best measured: R8).
// 296 CTAs x 7-8 upper-triangle 128x128 tiles, bi-major; A resident per chunk,
// B double-buffered via cp.async. mma.sync m16n8k32 e4m3 (fp32 accum), fused
// Cauchy epilogue (packed f32x2) with row + column sums.
// ---------------------------------------------------------------------------
#define LDS_STRIDE_B 144   // bytes per smem row: 128 data + 16 pad
#define TILE_BYTES (128 * LDS_STRIDE_B)        // 18432
#define PAIR_SMEM_BYTES (3 * TILE_BYTES)       // A + 2x B = 55296

__global__ void __launch_bounds__(256, 2) pair_kernel() {
    extern __shared__ __align__(16) char dynsm[];
    const uint32_t abase = smem_u32(dynsm);
    const uint32_t bbase0 = abase + TILE_BYTES;
    __shared__ float s_a[128];        // |x|^2 for A rows (raw)
    __shared__ float s_bb[2][128];    // |y|^2 for B rows (raw), per buffer

    const int tid = threadIdx.x;
    const int lane = tid & 31;
    const int wid = tid >> 5;

    // ---- chunk of tiles for this CTA ----
    const int b = blockIdx.x;
    const int start = b * 7 + (b < 8 ? b : 8);
    const int cnt = 7 + (b < 8 ? 1 : 0);
    int bi = 0, rem = start;
    while (rem >= NBLK - bi) { rem -= NBLK - bi; bi++; }
    int bj = bi + rem;

    auto issue_B = [&](int blk, int buf) {
        const char* g = (const char*)(g_X8 + (size_t)blk * 128 * KDIM);
        uint32_t sb = bbase0 + buf * TILE_BYTES;
#pragma unroll
        for (int it = 0; it < 4; it++) {
            int idx = tid + it * 256;          // 0..1023 (16B chunks)
            int r = idx >> 3, c = idx & 7;
            cp_async16(sb + r * LDS_STRIDE_B + c * 16, g + r * 128 + c * 16);
        }
        if (tid < 32)
            cp_async16(smem_u32(&s_bb[buf][0]) + tid * 16,
                       (const char*)(g_sq + blk * 128) + tid * 16);
    };
    auto issue_A = [&](int blk) {
        const char* g = (const char*)(g_X8 + (size_t)blk * 128 * KDIM);
#pragma unroll
        for (int it = 0; it < 4; it++) {
            int idx = tid + it * 256;
            int r = idx >> 3, c = idx & 7;
            cp_async16(abase + r * LDS_STRIDE_B + c * 16, g + r * 128 + c * 16);
        }
        if (tid < 32)
            cp_async16(smem_u32(&s_a[0]) + tid * 16,
                       (const char*)(g_sq + blk * 128) + tid * 16);
    };

    // ---- warp tiling: 4 (m) x 2 (n); warp tile = 32 x 64 ----
    const int rowbase = (wid & 3) * 32;
    const int colbase = (wid >> 2) * 64;
    const int lr = lane & 15;
    const int lc = lane >> 4;
    uint32_t aoff[2];
    uint32_t brel[4];
#pragma unroll
    for (int mi = 0; mi < 2; mi++)
        aoff[mi] = abase + (uint32_t)((rowbase + mi * 16 + lr) * LDS_STRIDE_B + lc * 16);
#pragma unroll
    for (int nq = 0; nq < 4; nq++)
        brel[nq] = (uint32_t)((colbase + nq * 16 + lr) * LDS_STRIDE_B + lc * 16);

    const int qr = lane >> 2;
    const int qc = (lane & 3) * 2;

    // ---- prime: A(bi) + B(bj) into buf 0 ----
    issue_A(bi);
    issue_B(bj, 0);
    cp_commit();
    bool need_cur = false;

    for (int i = 0; i < cnt; i++) {
        const int cur = i & 1;
        int nbi = bi, nbj = bj + 1;
        if (nbj == NBLK) { nbi++; nbj = nbi; }
        const bool have_next = (i + 1 < cnt);
        const bool same_bi = have_next && (nbi == bi);

        if (i > 0) __syncthreads();   // nobody still reads any buffer
        if (need_cur) {               // bi crossing: load A(bi)+B(bj,cur)
            issue_A(bi);
            issue_B(bj, cur);
            cp_commit();
        }
        if (same_bi) {                // prefetch next B during compute
            issue_B(nbj, cur ^ 1);
            cp_commit();
            asm volatile("cp.async.wait_group 1;" ::: "memory");
        } else {
            asm volatile("cp.async.wait_group 0;" ::: "memory");
        }
        __syncthreads();
        need_cur = have_next && (nbi != bi);

        const uint32_t bb = bbase0 + cur * TILE_BYTES;
        const float* s_b = s_bb[cur];
        const bool offdiag = (bi != bj);

        // ---- mma over K=128 fp8 (4 steps of 32) ----
        float acc[2][8][4];
#pragma unroll
        for (int mi = 0; mi < 2; mi++)
#pragma unroll
            for (int ni = 0; ni < 8; ni++)
#pragma unroll
                for (int r = 0; r < 4; r++) acc[mi][ni][r] = 0.f;

#pragma unroll
        for (int ks = 0; ks < 4; ks++) {
            uint32_t a[2][4];
            uint32_t bfr[8][2];
#pragma unroll
            for (int mi = 0; mi < 2; mi++) {
                asm volatile("ldmatrix.sync.aligned.m8n8.x4.shared.b16 {%0,%1,%2,%3}, [%4];"
                             : "=r"(a[mi][0]), "=r"(a[mi][1]), "=r"(a[mi][2]), "=r"(a[mi][3])
                             : "r"(aoff[mi] + ks * 32));
            }
#pragma unroll
            for (int nq = 0; nq < 4; nq++) {
                uint32_t r0, r1, r2, r3;
                asm volatile("ldmatrix.sync.aligned.m8n8.x4.shared.b16 {%0,%1,%2,%3}, [%4];"
                             : "=r"(r0), "=r"(r1), "=r"(r2), "=r"(r3)
                             : "r"(bb + brel[nq] + ks * 32));
                bfr[nq * 2 + 0][0] = r0; bfr[nq * 2 + 1][0] = r1;
                bfr[nq * 2 + 0][1] = r2; bfr[nq * 2 + 1][1] = r3;
            }
#pragma unroll
            for (int mi = 0; mi < 2; mi++)
#pragma unroll
                for (int ni = 0; ni < 8; ni++) {
                    asm volatile(
                        "mma.sync.aligned.m16n8k32.row.col.f32.e4m3.e4m3.f32 "
                        "{%0,%1,%2,%3}, {%4,%5,%6,%7}, {%8,%9}, {%0,%1,%2,%3};"
                        : "+f"(acc[mi][ni][0]), "+f"(acc[mi][ni][1]),
                          "+f"(acc[mi][ni][2]), "+f"(acc[mi][ni][3])
                        : "r"(a[mi][0]), "r"(a[mi][1]), "r"(a[mi][2]), "r"(a[mi][3]),
                          "r"(bfr[ni][0]), "r"(bfr[ni][1]));
                }
        }

        // ---- epilogue (packed f32x2): k = 1/(1 + |x|^2 + |y|^2 - 2 x.y) ----
        ull M2, ZER;
        PACK2(M2, -2.f, -2.f);
        PACK2(ZER, 0.f, 0.f);
        ull apk[2][2];
#pragma unroll
        for (int mi = 0; mi < 2; mi++) {
            float a0 = 1.f + s_a[rowbase + mi * 16 + qr];
            float a1 = 1.f + s_a[rowbase + mi * 16 + qr + 8];
            PACK2(apk[mi][0], a0, a0);
            PACK2(apk[mi][1], a1, a1);
        }
        ull rsp[2][2] = {{ZER, ZER}, {ZER, ZER}};

#pragma unroll
        for (int ni = 0; ni < 8; ni++) {
            float2 bp = *(const float2*)&s_b[colbase + ni * 8 + qc];
            ull bpk; PACK2(bpk, bp.x, bp.y);
            ull csp = ZER;
#pragma unroll
            for (int mi = 0; mi < 2; mi++) {
                ull t0, t1;
                ADDX2(t0, apk[mi][0], bpk);
                ADDX2(t1, apk[mi][1], bpk);
                ull a01, a23;
                PACK2(a01, acc[mi][ni][0], acc[mi][ni][1]);
                PACK2(a23, acc[mi][ni][2], acc[mi][ni][3]);
                ull d0, d1;
                FMAX2(d0, a01, M2, t0);
                FMAX2(d1, a23, M2, t1);
                float f00, f01, f10, f11;
                UNPACK2(f00, f01, d0);
                UNPACK2(f10, f11, d1);
                ull k01, k23;
                PACK2(k01, rcp_approx(f00), rcp_approx(f01));
                PACK2(k23, rcp_approx(f10), rcp_approx(f11));
                ADDX2(rsp[mi][0], rsp[mi][0], k01);
                ADDX2(rsp[mi][1], rsp[mi][1], k23);
                ADDX2(csp, csp, k01);
                ADDX2(csp, csp, k23);
            }
            if (offdiag) {
                float cs0, cs1;
                UNPACK2(cs0, cs1, csp);
                cs0 += __shfl_xor_sync(0xffffffff, cs0, 4);
                cs1 += __shfl_xor_sync(0xffffffff, cs1, 4);
                cs0 += __shfl_xor_sync(0xffffffff, cs0, 8);
                cs1 += __shfl_xor_sync(0xffffffff, cs1, 8);
                cs0 += __shfl_xor_sync(0xffffffff, cs0, 16);
                cs1 += __shfl_xor_sync(0xffffffff, cs1, 16);
                if (lane < 4) {
                    int cg = bj * 128 + colbase + ni * 8 + qc;
                    atomicAdd(g_row + cg, cs0);
                    atomicAdd(g_row + cg + 1, cs1);
                }
            }
        }
#pragma unroll
        for (int mi = 0; mi < 2; mi++) {
            float rs0, rs1, x, y;
            UNPACK2(x, y, rsp[mi][0]); rs0 = x + y;
            UNPACK2(x, y, rsp[mi][1]); rs1 = x + y;
            rs0 += __shfl_xor_sync(0xffffffff, rs0, 1);
            rs1 += __shfl_xor_sync(0xffffffff, rs1, 1);
            rs0 += __shfl_xor_sync(0xffffffff, rs0, 2);
            rs1 += __shfl_xor_sync(0xffffffff, rs1, 2);
            if ((lane & 3) == 0) {
                int r0 = bi * 128 + rowbase + mi * 16 + qr;
                atomicAdd(g_row + r0, rs0);
                atomicAdd(g_row + r0 + 8, rs1);
            }
        }

        bi = nbi; bj = nbj;
    }
}

// ---------------------------------------------------------------------------
// K3: parallel finalize.
// ---------------------------------------------------------------------------
__global__ void finalize_kernel(float* out) {
    const int tid = threadIdx.x;
    const int b = blockIdx.x;
    int row = b * 512 + tid;                 // 16*512 = 8192
    float an = __logf(g_row[row] - 1.0f);
    float ap = (tid < 256) ? g_logdiag[b * 256 + tid] : 0.f;
#pragma unroll
    for (int off = 16; off > 0; off >>= 1) {
        an += __shfl_xor_sync(0xffffffff, an, off);
        ap += __shfl_xor_sync(0xffffffff, ap, off);
    }
    __shared__ float sn[16], sp[16];
    int wid = tid >> 5, lane = tid & 31;
    if (lane == 0) { sn[wid] = an; sp[wid] = ap; }
    __syncthreads();
    if (tid == 0) {
        float tn = 0.f, tp = 0.f;
#pragma unroll
        for (int i = 0; i < 16; i++) { tn += sn[i]; tp += sp[i]; }
        atomicAdd(&g_part[0], tn);
        atomicAdd(&g_part[1], tp);
        __threadfence();
        unsigned int done = atomicAdd(&g_cnt, 1u);
        if (done == 15u) {
            float neg = *((volatile float*)&g_part[0]) / (2.0f * (float)BHALF);
            float pos = *((volatile float*)&g_part[1]) / (float)BHALF;
            out[0] = neg - pos;   // -(pos - neg)
        }
    }
}

// ---------------------------------------------------------------------------
extern "C" void kernel_launch(void* const* d_in, const int* in_sizes, int n_in,
                              void* d_out, int out_size) {
    const float* feat = (const float*)d_in[0];
    float* out = (float*)d_out;

    cudaFuncSetAttribute(pair_kernel,
                         cudaFuncAttributeMaxDynamicSharedMemorySize,
                         PAIR_SMEM_BYTES);

    prep_kernel<<<BHALF / 8, 256>>>(feat);
    pair_kernel<<<PCTAS, 256, PAIR_SMEM_BYTES>>>();
    finalize_kernel<<<16, 512>>>(out);
}

// round 17
// speedup vs baseline: 1.4294x; 1.0051x over previous
#include <cuda_runtime.h>
#include <cuda_bf16.h>
#include <cuda_fp16.h>
#include <cstdint>

#define NROWS 8192
#define BHALF 4096
#define KDIM  128
#define NBLK  64
#define PCTAS  296           // persistent CTAs (2 per SM)

typedef unsigned long long ull;

// Scratch (device globals — no allocation allowed in kernel_launch)
__device__ uint8_t g_X8[NROWS * KDIM];         // e4m3 copy of features
__device__ float g_sq[NROWS];                  // |x|^2 from fp8-rounded values
__device__ float g_row[NROWS];                 // full row sums of 8192x8192 kernel matrix
__device__ float g_logdiag[BHALF];             // log k12(i,i), fp32 path
__device__ float g_part[2];                    // partial sums for finalize
__device__ unsigned int g_cnt;                 // finalize block counter

static __device__ __forceinline__ uint32_t smem_u32(const void* p) {
    return (uint32_t)__cvta_generic_to_shared(p);
}

static __device__ __forceinline__ float rcp_approx(float x) {
    float r;
    asm("rcp.approx.ftz.f32 %0, %1;" : "=f"(r) : "f"(x));
    return r;
}

static __device__ __forceinline__ void cp_async16(uint32_t dst, const void* src) {
    asm volatile("cp.async.cg.shared.global [%0], [%1], 16;"
                 :: "r"(dst), "l"(src));
}
static __device__ __forceinline__ void cp_commit() {
    asm volatile("cp.async.commit_group;" ::: "memory");
}

// packed fp32 pair helpers (Blackwell FFMA2 path)
#define PACK2(o, lo, hi)  asm("mov.b64 %0, {%1, %2};" : "=l"(o) : "f"(lo), "f"(hi))
#define UNPACK2(lo, hi, i) asm("mov.b64 {%0, %1}, %2;" : "=f"(lo), "=f"(hi) : "l"(i))
#define ADDX2(o, a, b)     asm("add.rn.f32x2 %0, %1, %2;" : "=l"(o) : "l"(a), "l"(b))
#define FMAX2(o, a, b, c)  asm("fma.rn.f32x2 %0, %1, %2, %3;" : "=l"(o) : "l"(a), "l"(b), "l"(c))

// fp8 pack: lo = x, hi = y (cvt packs 2nd src operand into low half)
static __device__ __forceinline__ uint16_t f2_to_e4m3x2(float x, float y) {
    uint16_t r;
    asm("cvt.rn.satfinite.e4m3x2.f32 %0, %1, %2;" : "=h"(r) : "f"(y), "f"(x));
    return r;
}
static __device__ __forceinline__ float2 e4m3x2_to_f2(uint16_t q) {
    uint32_t h2;
    asm("cvt.rn.f16x2.e4m3x2 %0, %1;" : "=r"(h2) : "h"(q));
    return __half22float2(*(__half2*)&h2);
}

// ---------------------------------------------------------------------------
// K1: fused prep + diag. One warp per pair (i, i+4096).
// Converts to e4m3, computes |x|^2 from dequantized fp8 (consistent with mma),
// fp32 diagonal for the pos term.
// ---------------------------------------------------------------------------
__global__ void prep_kernel(const float* __restrict__ feat) {
    int w = threadIdx.x >> 5;
    int lane = threadIdx.x & 31;
    int p = blockIdx.x * 8 + w;           // 0..4095
    if (blockIdx.x == 0 && threadIdx.x == 0) {
        g_part[0] = 0.f; g_part[1] = 0.f; g_cnt = 0u;
    }
    if (p >= BHALF) return;
    float4 v1 = ((const float4*)(feat + (size_t)p * KDIM))[lane];
    float4 v2 = ((const float4*)(feat + (size_t)(p + BHALF) * KDIM))[lane];

    uint16_t q1a = f2_to_e4m3x2(v1.x, v1.y), q1b = f2_to_e4m3x2(v1.z, v1.w);
    uint16_t q2a = f2_to_e4m3x2(v2.x, v2.y), q2b = f2_to_e4m3x2(v2.z, v2.w);
    ((uint32_t*)(g_X8 + (size_t)p * KDIM))[lane] = (uint32_t)q1a | ((uint32_t)q1b << 16);
    ((uint32_t*)(g_X8 + (size_t)(p + BHALF) * KDIM))[lane] = (uint32_t)q2a | ((uint32_t)q2b << 16);

    float2 r1a = e4m3x2_to_f2(q1a), r1b = e4m3x2_to_f2(q1b);
    float2 r2a = e4m3x2_to_f2(q2a), r2b = e4m3x2_to_f2(q2b);
    float sb1 = r1a.x * r1a.x + r1a.y * r1a.y + r1b.x * r1b.x + r1b.y * r1b.y;
    float sb2 = r2a.x * r2a.x + r2a.y * r2a.y + r2b.x * r2b.x + r2b.y * r2b.y;
    float t1 = v1.x * v1.x + v1.y * v1.y + v1.z * v1.z + v1.w * v1.w;
    float t2 = v2.x * v2.x + v2.y * v2.y + v2.z * v2.z + v2.w * v2.w;
    float sd = v1.x * v2.x + v1.y * v2.y + v1.z * v2.z + v1.w * v2.w;

#pragma unroll
    for (int off = 16; off > 0; off >>= 1) {
        sb1 += __shfl_xor_sync(0xffffffff, sb1, off);
        sb2 += __shfl_xor_sync(0xffffffff, sb2, off);
        t1  += __shfl_xor_sync(0xffffffff, t1, off);
        t2  += __shfl_xor_sync(0xffffffff, t2, off);
        sd  += __shfl_xor_sync(0xffffffff, sd, off);
    }
    if (lane == 0) {
        g_sq[p] = sb1;
        g_sq[p + BHALF] = sb2;
        g_row[p] = 0.f;
        g_row[p + BHALF] = 0.f;
        float d2v = fmaxf(t1 + t2 - 2.f * sd, 0.f);
        g_logdiag[p] = -log1pf(d2v);
    }
}

// ---------------------------------------------------------------------------
// K2: persistent, software-pipelined fp8 pairwise kernel (best measured: R8).
// 296 CTAs x 7-8 upper-triangle 128x128 tiles, bi-major; A resident per chunk,
// B double-buffered via cp.async. mma.sync m16n8k32 e4m3 (fp32 accum), fused
// Cauchy epilogue (packed f32x2) with row + column sums.
// ---------------------------------------------------------------------------
#define LDS_STRIDE_B 144   // bytes per smem row: 128 data + 16 pad
#define TILE_BYTES (128 * LDS_STRIDE_B)        // 18432
#define PAIR_SMEM_BYTES (3 * TILE_BYTES)       // A + 2x B = 55296

__global__ void __launch_bounds__(256, 2) pair_kernel() {
    extern __shared__ __align__(16) char dynsm[];
    const uint32_t abase = smem_u32(dynsm);
    const uint32_t bbase0 = abase + TILE_BYTES;
    __shared__ float s_a[128];        // |x|^2 for A rows (raw)
    __shared__ float s_bb[2][128];    // |y|^2 for B rows (raw), per buffer

    const int tid = threadIdx.x;
    const int lane = tid & 31;
    const int wid = tid >> 5;

    // ---- chunk of tiles for this CTA ----
    const int b = blockIdx.x;
    const int start = b * 7 + (b < 8 ? b : 8);
    const int cnt = 7 + (b < 8 ? 1 : 0);
    int bi = 0, rem = start;
    while (rem >= NBLK - bi) { rem -= NBLK - bi; bi++; }
    int bj = bi + rem;

    auto issue_B = [&](int blk, int buf) {
        const char* g = (const char*)(g_X8 + (size_t)blk * 128 * KDIM);
        uint32_t sb = bbase0 + buf * TILE_BYTES;
#pragma unroll
        for (int it = 0; it < 4; it++) {
            int idx = tid + it * 256;          // 0..1023 (16B chunks)
            int r = idx >> 3, c = idx & 7;
            cp_async16(sb + r * LDS_STRIDE_B + c * 16, g + r * 128 + c * 16);
        }
        if (tid < 32)
            cp_async16(smem_u32(&s_bb[buf][0]) + tid * 16,
                       (const char*)(g_sq + blk * 128) + tid * 16);
    };
    auto issue_A = [&](int blk) {
        const char* g = (const char*)(g_X8 + (size_t)blk * 128 * KDIM);
#pragma unroll
        for (int it = 0; it < 4; it++) {
            int idx = tid + it * 256;
            int r = idx >> 3, c = idx & 7;
            cp_async16(abase + r * LDS_STRIDE_B + c * 16, g + r * 128 + c * 16);
        }
        if (tid < 32)
            cp_async16(smem_u32(&s_a[0]) + tid * 16,
                       (const char*)(g_sq + blk * 128) + tid * 16);
    };

    // ---- warp tiling: 4 (m) x 2 (n); warp tile = 32 x 64 ----
    const int rowbase = (wid & 3) * 32;
    const int colbase = (wid >> 2) * 64;
    const int lr = lane & 15;
    const int lc = lane >> 4;
    uint32_t aoff[2];
    uint32_t brel[4];
#pragma unroll
    for (int mi = 0; mi < 2; mi++)
        aoff[mi] = abase + (uint32_t)((rowbase + mi * 16 + lr) * LDS_STRIDE_B + lc * 16);
#pragma unroll
    for (int nq = 0; nq < 4; nq++)
        brel[nq] = (uint32_t)((colbase + nq * 16 + lr) * LDS_STRIDE_B + lc * 16);

    const int qr = lane >> 2;
    const int qc = (lane & 3) * 2;

    // ---- prime: A(bi) + B(bj) into buf 0 ----
    issue_A(bi);
    issue_B(bj, 0);
    cp_commit();
    bool need_cur = false;

    for (int i = 0; i < cnt; i++) {
        const int cur = i & 1;
        int nbi = bi, nbj = bj + 1;
        if (nbj == NBLK) { nbi++; nbj = nbi; }
        const bool have_next = (i + 1 < cnt);
        const bool same_bi = have_next && (nbi == bi);

        if (i > 0) __syncthreads();   // nobody still reads any buffer
        if (need_cur) {               // bi crossing: load A(bi)+B(bj,cur)
            issue_A(bi);
            issue_B(bj, cur);
            cp_commit();
        }
        if (same_bi) {                // prefetch next B during compute
            issue_B(nbj, cur ^ 1);
            cp_commit();
            asm volatile("cp.async.wait_group 1;" ::: "memory");
        } else {
            asm volatile("cp.async.wait_group 0;" ::: "memory");
        }
        __syncthreads();
        need_cur = have_next && (nbi != bi);

        const uint32_t bb = bbase0 + cur * TILE_BYTES;
        const float* s_b = s_bb[cur];
        const bool offdiag = (bi != bj);

        // ---- mma over K=128 fp8 (4 steps of 32) ----
        float acc[2][8][4];
#pragma unroll
        for (int mi = 0; mi < 2; mi++)
#pragma unroll
            for (int ni = 0; ni < 8; ni++)
#pragma unroll
                for (int r = 0; r < 4; r++) acc[mi][ni][r] = 0.f;

#pragma unroll
        for (int ks = 0; ks < 4; ks++) {
            uint32_t a[2][4];
            uint32_t bfr[8][2];
#pragma unroll
            for (int mi = 0; mi < 2; mi++) {
                asm volatile("ldmatrix.sync.aligned.m8n8.x4.shared.b16 {%0,%1,%2,%3}, [%4];"
                             : "=r"(a[mi][0]), "=r"(a[mi][1]), "=r"(a[mi][2]), "=r"(a[mi][3])
                             : "r"(aoff[mi] + ks * 32));
            }
#pragma unroll
            for (int nq = 0; nq < 4; nq++) {
                uint32_t r0, r1, r2, r3;
                asm volatile("ldmatrix.sync.aligned.m8n8.x4.shared.b16 {%0,%1,%2,%3}, [%4];"
                             : "=r"(r0), "=r"(r1), "=r"(r2), "=r"(r3)
                             : "r"(bb + brel[nq] + ks * 32));
                bfr[nq * 2 + 0][0] = r0; bfr[nq * 2 + 1][0] = r1;
                bfr[nq * 2 + 0][1] = r2; bfr[nq * 2 + 1][1] = r3;
            }
#pragma unroll
            for (int mi = 0; mi < 2; mi++)
#pragma unroll
                for (int ni = 0; ni < 8; ni++) {
                    asm volatile(
                        "mma.sync.aligned.m16n8k32.row.col.f32.e4m3.e4m3.f32 "
                        "{%0,%1,%2,%3}, {%4,%5,%6,%7}, {%8,%9}, {%0,%1,%2,%3};"
                        : "+f"(acc[mi][ni][0]), "+f"(acc[mi][ni][1]),
                          "+f"(acc[mi][ni][2]), "+f"(acc[mi][ni][3])
                        : "r"(a[mi][0]), "r"(a[mi][1]), "r"(a[mi][2]), "r"(a[mi][3]),
                          "r"(bfr[ni][0]), "r"(bfr[ni][1]));
                }
        }

        // ---- epilogue (packed f32x2): k = 1/(1 + |x|^2 + |y|^2 - 2 x.y) ----
        ull M2, ZER;
        PACK2(M2, -2.f, -2.f);
        PACK2(ZER, 0.f, 0.f);
        ull apk[2][2];
#pragma unroll
        for (int mi = 0; mi < 2; mi++) {
            float a0 = 1.f + s_a[rowbase + mi * 16 + qr];
            float a1 = 1.f + s_a[rowbase + mi * 16 + qr + 8];
            PACK2(apk[mi][0], a0, a0);
            PACK2(apk[mi][1], a1, a1);
        }
        ull rsp[2][2] = {{ZER, ZER}, {ZER, ZER}};

#pragma unroll
        for (int ni = 0; ni < 8; ni++) {
            float2 bp = *(const float2*)&s_b[colbase + ni * 8 + qc];
            ull bpk; PACK2(bpk, bp.x, bp.y);
            ull csp = ZER;
#pragma unroll
            for (int mi = 0; mi < 2; mi++) {
                ull t0, t1;
                ADDX2(t0, apk[mi][0], bpk);
                ADDX2(t1, apk[mi][1], bpk);
                ull a01, a23;
                PACK2(a01, acc[mi][ni][0], acc[mi][ni][1]);
                PACK2(a23, acc[mi][ni][2], acc[mi][ni][3]);
                ull d0, d1;
                FMAX2(d0, a01, M2, t0);
                FMAX2(d1, a23, M2, t1);
                float f00, f01, f10, f11;
                UNPACK2(f00, f01, d0);
                UNPACK2(f10, f11, d1);
                ull k01, k23;
                PACK2(k01, rcp_approx(f00), rcp_approx(f01));
                PACK2(k23, rcp_approx(f10), rcp_approx(f11));
                ADDX2(rsp[mi][0], rsp[mi][0], k01);
                ADDX2(rsp[mi][1], rsp[mi][1], k23);
                ADDX2(csp, csp, k01);
                ADDX2(csp, csp, k23);
            }
            if (offdiag) {
                float cs0, cs1;
                UNPACK2(cs0, cs1, csp);
                cs0 += __shfl_xor_sync(0xffffffff, cs0, 4);
                cs1 += __shfl_xor_sync(0xffffffff, cs1, 4);
                cs0 += __shfl_xor_sync(0xffffffff, cs0, 8);
                cs1 += __shfl_xor_sync(0xffffffff, cs1, 8);
                cs0 += __shfl_xor_sync(0xffffffff, cs0, 16);
                cs1 += __shfl_xor_sync(0xffffffff, cs1, 16);
                if (lane < 4) {
                    int cg = bj * 128 + colbase + ni * 8 + qc;
                    atomicAdd(g_row + cg, cs0);
                    atomicAdd(g_row + cg + 1, cs1);
                }
            }
        }
#pragma unroll
        for (int mi = 0; mi < 2; mi++) {
            float rs0, rs1, x, y;
            UNPACK2(x, y, rsp[mi][0]); rs0 = x + y;
            UNPACK2(x, y, rsp[mi][1]); rs1 = x + y;
            rs0 += __shfl_xor_sync(0xffffffff, rs0, 1);
            rs1 += __shfl_xor_sync(0xffffffff, rs1, 1);
            rs0 += __shfl_xor_sync(0xffffffff, rs0, 2);
            rs1 += __shfl_xor_sync(0xffffffff, rs1, 2);
            if ((lane & 3) == 0) {
                int r0 = bi * 128 + rowbase + mi * 16 + qr;
                atomicAdd(g_row + r0, rs0);
                atomicAdd(g_row + r0 + 8, rs1);
            }
        }

        bi = nbi; bj = nbj;
    }
}

// ---------------------------------------------------------------------------
// K3: parallel finalize.
// ---------------------------------------------------------------------------
__global__ void finalize_kernel(float* out) {
    const int tid = threadIdx.x;
    const int b = blockIdx.x;
    int row = b * 512 + tid;                 // 16*512 = 8192
    float an = __logf(g_row[row] - 1.0f);
    float ap = (tid < 256) ? g_logdiag[b * 256 + tid] : 0.f;
#pragma unroll
    for (int off = 16; off > 0; off >>= 1) {
        an += __shfl_xor_sync(0xffffffff, an, off);
        ap += __shfl_xor_sync(0xffffffff, ap, off);
    }
    __shared__ float sn[16], sp[16];
    int wid = tid >> 5, lane = tid & 31;
    if (lane == 0) { sn[wid] = an; sp[wid] = ap; }
    __syncthreads();
    if (tid == 0) {
        float tn = 0.f, tp = 0.f;
#pragma unroll
        for (int i = 0; i < 16; i++) { tn += sn[i]; tp += sp[i]; }
        atomicAdd(&g_part[0], tn);
        atomicAdd(&g_part[1], tp);
        __threadfence();
        unsigned int done = atomicAdd(&g_cnt, 1u);
        if (done == 15u) {
            float neg = *((volatile float*)&g_part[0]) / (2.0f * (float)BHALF);
            float pos = *((volatile float*)&g_part[1]) / (float)BHALF;
            out[0] = neg - pos;   // -(pos - neg)
        }
    }
}

// ---------------------------------------------------------------------------
extern "C" void kernel_launch(void* const* d_in, const int* in_sizes, int n_in,
                              void* d_out, int out_size) {
    const float* feat = (const float*)d_in[0];
    float* out = (float*)d_out;

    cudaFuncSetAttribute(pair_kernel,
                         cudaFuncAttributeMaxDynamicSharedMemorySize,
                         PAIR_SMEM_BYTES);

    prep_kernel<<<BHALF / 8, 256>>>(feat);
    pair_kernel<<<PCTAS, 256, PAIR_SMEM_BYTES>>>();
    finalize_kernel<<<16, 512>>>(out);
}